// round 4
// baseline (speedup 1.0000x reference)
#include <cuda_runtime.h>

#define N_RAYS   65536
#define N_SAMPLES 128

// Persistent grid-stride: one warp processes ~7 rays sequentially.
// Lane l owns samples [4l, 4l+4) of the current ray.
// weight_i = max(0, sig_i - sig_{i+1}) / sig_0  (telescoped cumprod),
// weight_0 = weight_{S-1} = 0.
// pixel = sum(w*(c-bg)) + bg  (folds wsum reduction away).
__global__ __launch_bounds__(256) void neus_render_kernel(
    const float* __restrict__ sdf,      // [R, S]
    const float* __restrict__ color,    // [R, S, 3]
    const float* __restrict__ z_vals,   // [R, S]
    const float* __restrict__ s_ptr,    // [1]
    const float* __restrict__ bg,       // [3]
    float* __restrict__ out)            // [R*3 pixel | R invdepth | R*S weight]
{
    const unsigned FULL = 0xffffffffu;
    const int lane = threadIdx.x & 31;
    const int warp_global = (blockIdx.x * blockDim.x + threadIdx.x) >> 5;
    const int total_warps = (gridDim.x * blockDim.x) >> 5;

    const float s   = s_ptr[0];
    const float bgr = bg[0], bgg = bg[1], bgb = bg[2];

    float* const out_pixel    = out;
    float* const out_invdepth = out + (size_t)N_RAYS * 3;
    float* const out_weight   = out + (size_t)N_RAYS * 4;

    for (int ray = warp_global; ray < N_RAYS; ray += total_warps) {
        // ---- streaming loads up front (max MLP, pipelines across iterations) ----
        const float4 sd = __ldcs(reinterpret_cast<const float4*>(sdf + (size_t)ray * N_SAMPLES) + lane);
        const float4 zz = __ldcs(reinterpret_cast<const float4*>(z_vals + (size_t)ray * N_SAMPLES) + lane);
        const float4* c4 = reinterpret_cast<const float4*>(
            color + ((size_t)ray * N_SAMPLES + lane * 4) * 3);
        const float4 c0 = __ldcs(c4 + 0);  // s0.r s0.g s0.b s1.r
        const float4 c1 = __ldcs(c4 + 1);  // s1.g s1.b s2.r s2.g
        const float4 c2 = __ldcs(c4 + 2);  // s2.b s3.r s3.g s3.b

        // ---- sdf -> sigmoid (MUFU fast paths) ----
        float sg0 = __fdividef(1.0f, 1.0f + __expf(-sd.x * s));
        float sg1 = __fdividef(1.0f, 1.0f + __expf(-sd.y * s));
        float sg2 = __fdividef(1.0f, 1.0f + __expf(-sd.z * s));
        float sg3 = __fdividef(1.0f, 1.0f + __expf(-sd.w * s));

        float sg_next   = __shfl_down_sync(FULL, sg0, 1); // sigmoid of sample 4l+4
        float sig_first = __shfl_sync(FULL, sg0, 0);      // sigmoid of sample 0
        float inv_sig0  = __fdividef(1.0f, sig_first);

        // ---- weights ----
        float w0 = (lane == 0)  ? 0.0f : fmaxf(0.0f, sg0 - sg1) * inv_sig0;
        float w1 =                       fmaxf(0.0f, sg1 - sg2) * inv_sig0;
        float w2 =                       fmaxf(0.0f, sg2 - sg3) * inv_sig0;
        float w3 = (lane == 31) ? 0.0f : fmaxf(0.0f, sg3 - sg_next) * inv_sig0;

        // ---- inverse depth ----
        float invd = __fdividef(w0, zz.x) + __fdividef(w1, zz.y)
                   + __fdividef(w2, zz.z) + __fdividef(w3, zz.w);

        // ---- color accumulation with bg folded in ----
        float pr = w0 * (c0.x - bgr) + w1 * (c0.w - bgr) + w2 * (c1.z - bgr) + w3 * (c2.y - bgr);
        float pg = w0 * (c0.y - bgg) + w1 * (c1.x - bgg) + w2 * (c1.w - bgg) + w3 * (c2.z - bgg);
        float pb = w0 * (c0.z - bgb) + w1 * (c1.y - bgb) + w2 * (c2.x - bgb) + w3 * (c2.w - bgb);

        // ---- write weights (coalesced float4, streaming) ----
        __stcs(reinterpret_cast<float4*>(out_weight + (size_t)ray * N_SAMPLES) + lane,
               make_float4(w0, w1, w2, w3));

        // ---- warp reductions (4 values) ----
        #pragma unroll
        for (int off = 16; off > 0; off >>= 1) {
            pr   += __shfl_down_sync(FULL, pr,   off);
            pg   += __shfl_down_sync(FULL, pg,   off);
            pb   += __shfl_down_sync(FULL, pb,   off);
            invd += __shfl_down_sync(FULL, invd, off);
        }

        if (lane == 0) {
            out_pixel[ray * 3 + 0] = pr + bgr;
            out_pixel[ray * 3 + 1] = pg + bgg;
            out_pixel[ray * 3 + 2] = pb + bgb;
            out_invdepth[ray] = invd;
        }
    }
}

extern "C" void kernel_launch(void* const* d_in, const int* in_sizes, int n_in,
                              void* d_out, int out_size) {
    const float* sdf    = (const float*)d_in[0];
    const float* color  = (const float*)d_in[1];
    const float* z_vals = (const float*)d_in[2];
    const float* s      = (const float*)d_in[3];
    const float* bg     = (const float*)d_in[4];
    float* out = (float*)d_out;

    // Persistent: ~8 CTAs per SM (GB300 = 152 SMs), single wave, grid-stride.
    const int threads = 256;
    const int blocks  = 152 * 8;
    neus_render_kernel<<<blocks, threads>>>(sdf, color, z_vals, s, bg, out);
}

// round 5
// speedup vs baseline: 1.1281x; 1.1281x over previous
#include <cuda_runtime.h>

#define N_RAYS   65536
#define N_SAMPLES 128

// Persistent grid-stride, software-pipelined: next ray's loads are issued
// before the current ray's reduction epilogue, keeping DRAM requests in
// flight through the ~400-cycle shuffle/MUFU tail.
// Lane l owns samples [4l, 4l+4). Telescoped cumprod:
//   weight_i = max(0, sig_i - sig_{i+1}) / sig_0, weight_0 = weight_{S-1} = 0.
// pixel = sum(w*(c-bg)) + bg.
__global__ void __launch_bounds__(256, 4) neus_render_kernel(
    const float* __restrict__ sdf,      // [R, S]
    const float* __restrict__ color,    // [R, S, 3]
    const float* __restrict__ z_vals,   // [R, S]
    const float* __restrict__ s_ptr,    // [1]
    const float* __restrict__ bg,       // [3]
    float* __restrict__ out)            // [R*3 pixel | R invdepth | R*S weight]
{
    const unsigned FULL = 0xffffffffu;
    const int lane = threadIdx.x & 31;
    int ray = (blockIdx.x * blockDim.x + threadIdx.x) >> 5;
    const int total_warps = (gridDim.x * blockDim.x) >> 5;
    if (ray >= N_RAYS) return;

    const float s   = s_ptr[0];
    const float bgr = bg[0], bgg = bg[1], bgb = bg[2];

    float* const out_pixel    = out;
    float* const out_invdepth = out + (size_t)N_RAYS * 3;
    float* const out_weight   = out + (size_t)N_RAYS * 4;

    // ---- prologue loads for the first ray ----
    float4 sd = __ldcs(reinterpret_cast<const float4*>(sdf + (size_t)ray * N_SAMPLES) + lane);
    float4 zz = __ldcs(reinterpret_cast<const float4*>(z_vals + (size_t)ray * N_SAMPLES) + lane);
    const float4* c4 = reinterpret_cast<const float4*>(
        color + ((size_t)ray * N_SAMPLES + lane * 4) * 3);
    float4 c0 = __ldcs(c4 + 0);
    float4 c1 = __ldcs(c4 + 1);
    float4 c2 = __ldcs(c4 + 2);

    while (true) {
        const int nray = ray + total_warps;
        const bool more = (nray < N_RAYS);

        // ---- sdf -> sigmoid (MUFU fast paths) ----
        float sg0 = __fdividef(1.0f, 1.0f + __expf(-sd.x * s));
        float sg1 = __fdividef(1.0f, 1.0f + __expf(-sd.y * s));
        float sg2 = __fdividef(1.0f, 1.0f + __expf(-sd.z * s));
        float sg3 = __fdividef(1.0f, 1.0f + __expf(-sd.w * s));

        float sg_next   = __shfl_down_sync(FULL, sg0, 1); // sigmoid of sample 4l+4
        float sig_first = __shfl_sync(FULL, sg0, 0);      // sigmoid of sample 0
        float inv_sig0  = __fdividef(1.0f, sig_first);

        // ---- weights ----
        float w0 = (lane == 0)  ? 0.0f : fmaxf(0.0f, sg0 - sg1) * inv_sig0;
        float w1 =                       fmaxf(0.0f, sg1 - sg2) * inv_sig0;
        float w2 =                       fmaxf(0.0f, sg2 - sg3) * inv_sig0;
        float w3 = (lane == 31) ? 0.0f : fmaxf(0.0f, sg3 - sg_next) * inv_sig0;

        // ---- inverse depth + color (consume current registers) ----
        float invd = __fdividef(w0, zz.x) + __fdividef(w1, zz.y)
                   + __fdividef(w2, zz.z) + __fdividef(w3, zz.w);

        float pr = w0 * (c0.x - bgr) + w1 * (c0.w - bgr) + w2 * (c1.z - bgr) + w3 * (c2.y - bgr);
        float pg = w0 * (c0.y - bgg) + w1 * (c1.x - bgg) + w2 * (c1.w - bgg) + w3 * (c2.z - bgg);
        float pb = w0 * (c0.z - bgb) + w1 * (c1.y - bgb) + w2 * (c2.x - bgb) + w3 * (c2.w - bgb);

        // ---- fire-and-forget weight store ----
        __stcs(reinterpret_cast<float4*>(out_weight + (size_t)ray * N_SAMPLES) + lane,
               make_float4(w0, w1, w2, w3));

        // ---- PREFETCH next ray (in flight through the reduction tail) ----
        float4 nsd, nzz, nc0, nc1, nc2;
        if (more) {
            nsd = __ldcs(reinterpret_cast<const float4*>(sdf + (size_t)nray * N_SAMPLES) + lane);
            nzz = __ldcs(reinterpret_cast<const float4*>(z_vals + (size_t)nray * N_SAMPLES) + lane);
            const float4* nc4 = reinterpret_cast<const float4*>(
                color + ((size_t)nray * N_SAMPLES + lane * 4) * 3);
            nc0 = __ldcs(nc4 + 0);
            nc1 = __ldcs(nc4 + 1);
            nc2 = __ldcs(nc4 + 2);
        }

        // ---- warp reductions (4 values) ----
        #pragma unroll
        for (int off = 16; off > 0; off >>= 1) {
            pr   += __shfl_down_sync(FULL, pr,   off);
            pg   += __shfl_down_sync(FULL, pg,   off);
            pb   += __shfl_down_sync(FULL, pb,   off);
            invd += __shfl_down_sync(FULL, invd, off);
        }

        if (lane == 0) {
            out_pixel[ray * 3 + 0] = pr + bgr;
            out_pixel[ray * 3 + 1] = pg + bgg;
            out_pixel[ray * 3 + 2] = pb + bgb;
            out_invdepth[ray] = invd;
        }

        if (!more) break;
        ray = nray;
        sd = nsd; zz = nzz; c0 = nc0; c1 = nc1; c2 = nc2;
    }
}

extern "C" void kernel_launch(void* const* d_in, const int* in_sizes, int n_in,
                              void* d_out, int out_size) {
    const float* sdf    = (const float*)d_in[0];
    const float* color  = (const float*)d_in[1];
    const float* z_vals = (const float*)d_in[2];
    const float* s      = (const float*)d_in[3];
    const float* bg     = (const float*)d_in[4];
    float* out = (float*)d_out;

    // 4 CTAs/SM (64-reg budget via launch_bounds), single wave on 152 SMs.
    const int threads = 256;
    const int blocks  = 152 * 4;
    neus_render_kernel<<<blocks, threads>>>(sdf, color, z_vals, s, bg, out);
}